// round 1
// baseline (speedup 1.0000x reference)
#include <cuda_runtime.h>
#include <cstdint>

// LoLa: out[m, 0] = sum_p x[m,p]; out[m, 1:513] = x[m,:]; out[m, 513:1025] = x[m,:] @ w
// M = 131072, K = 512, NOUT = 512, OUT_COLS = 1025.

#define M_TOTAL   131072
#define KDIM      512
#define NOUT      512
#define OUT_COLS  1025

#define MT 128          // CTA M tile
#define NT 128          // CTA N tile (4 n-tiles cover NOUT=512)
#define KT 32           // K step

#define XS_STRIDE 36    // bank = (36r+c)%32 = (4r+c)%32 -> conflict-free frag loads
#define WS_STRIDE 136   // bank = (136k+n)%32 = (8k+n)%32 -> conflict-free frag loads

__device__ __forceinline__ uint32_t f2tf32(float f) {
    uint32_t u;
    asm("cvt.rna.tf32.f32 %0, %1;" : "=r"(u) : "f"(f));
    return u;
}

__global__ __launch_bounds__(256, 2)
void lola_fused_kernel(const float* __restrict__ x,
                       const float* __restrict__ w,
                       float* __restrict__ out)
{
    __shared__ float    xs[MT][XS_STRIDE];   // raw fp32 x tile (exact copy path needs fp32)
    __shared__ uint32_t ws[KT][WS_STRIDE];   // w tile pre-converted to tf32 bits
    __shared__ float    rowsum[MT];

    const int nb   = blockIdx.x;             // 0..3
    const int mb   = blockIdx.y;             // 0..1023
    const int m0   = mb * MT;
    const int n0   = nb * NT;
    const int tid  = threadIdx.x;
    const int lane = tid & 31;
    const int warp = tid >> 5;
    const int warp_m = warp >> 2;            // 0..1  -> m offset warp_m*64
    const int warp_n = warp & 3;             // 0..3  -> n offset warp_n*32
    const bool do_extra = (nb == 0);         // this CTA also writes copy + rowsum

    if (do_extra && tid < MT) rowsum[tid] = 0.0f;
    __syncthreads();

    float acc[4][4][4];                      // [mfrag][nfrag][c0..c3]
    #pragma unroll
    for (int i = 0; i < 4; i++)
        #pragma unroll
        for (int j = 0; j < 4; j++)
            #pragma unroll
            for (int k = 0; k < 4; k++)
                acc[i][j][k] = 0.0f;

    for (int k0 = 0; k0 < KDIM; k0 += KT) {
        // ---- stage x tile: 128x32 floats = 1024 float4, 4 per thread ----
        #pragma unroll
        for (int i = 0; i < 4; i++) {
            int idx = tid + i * 256;         // 0..1023
            int r   = idx >> 3;              // 0..127
            int c   = (idx & 7) * 4;         // 0..28
            float4 v = *(const float4*)&x[(size_t)(m0 + r) * KDIM + k0 + c];
            *(float4*)&xs[r][c] = v;
            if (do_extra) {
                // identity-copy columns (offset 1, odd alignment -> scalar stores)
                float* o = &out[(size_t)(m0 + r) * OUT_COLS + 1 + k0 + c];
                o[0] = v.x; o[1] = v.y; o[2] = v.z; o[3] = v.w;
                atomicAdd(&rowsum[r], v.x + v.y + v.z + v.w);
            }
        }
        // ---- stage w tile: 32x128 floats, converted to tf32 ----
        #pragma unroll
        for (int i = 0; i < 4; i++) {
            int idx = tid + i * 256;
            int r   = idx >> 5;              // 0..31
            int c   = (idx & 31) * 4;        // 0..124
            float4 v = *(const float4*)&w[(size_t)(k0 + r) * NOUT + n0 + c];
            uint4 t;
            t.x = f2tf32(v.x); t.y = f2tf32(v.y); t.z = f2tf32(v.z); t.w = f2tf32(v.w);
            *(uint4*)&ws[r][c] = t;
        }
        __syncthreads();

        // ---- compute: KT/8 = 4 mma k-steps ----
        #pragma unroll
        for (int kk = 0; kk < KT; kk += 8) {
            uint32_t bfrag[4][2];
            #pragma unroll
            for (int nf = 0; nf < 4; nf++) {
                int col = warp_n * 32 + nf * 8 + (lane >> 2);
                bfrag[nf][0] = ws[kk + (lane & 3)][col];
                bfrag[nf][1] = ws[kk + (lane & 3) + 4][col];
            }
            uint32_t afrag[4][4];
            #pragma unroll
            for (int mf = 0; mf < 4; mf++) {
                int row = warp_m * 64 + mf * 16 + (lane >> 2);
                int c0  = kk + (lane & 3);
                afrag[mf][0] = f2tf32(xs[row][c0]);
                afrag[mf][1] = f2tf32(xs[row + 8][c0]);
                afrag[mf][2] = f2tf32(xs[row][c0 + 4]);
                afrag[mf][3] = f2tf32(xs[row + 8][c0 + 4]);
            }
            #pragma unroll
            for (int mf = 0; mf < 4; mf++) {
                #pragma unroll
                for (int nf = 0; nf < 4; nf++) {
                    asm volatile(
                        "mma.sync.aligned.m16n8k8.row.col.f32.tf32.tf32.f32 "
                        "{%0,%1,%2,%3}, {%4,%5,%6,%7}, {%8,%9}, {%0,%1,%2,%3};"
                        : "+f"(acc[mf][nf][0]), "+f"(acc[mf][nf][1]),
                          "+f"(acc[mf][nf][2]), "+f"(acc[mf][nf][3])
                        : "r"(afrag[mf][0]), "r"(afrag[mf][1]),
                          "r"(afrag[mf][2]), "r"(afrag[mf][3]),
                          "r"(bfrag[nf][0]), "r"(bfrag[nf][1]));
                }
            }
        }
        __syncthreads();
    }

    // ---- epilogue: GEMM columns (513..1024) ----
    #pragma unroll
    for (int mf = 0; mf < 4; mf++) {
        int row = m0 + warp_m * 64 + mf * 16 + (lane >> 2);
        #pragma unroll
        for (int nf = 0; nf < 4; nf++) {
            int col = 513 + n0 + warp_n * 32 + nf * 8 + (lane & 3) * 2;
            out[(size_t)row * OUT_COLS + col]           = acc[mf][nf][0];
            out[(size_t)row * OUT_COLS + col + 1]       = acc[mf][nf][1];
            out[(size_t)(row + 8) * OUT_COLS + col]     = acc[mf][nf][2];
            out[(size_t)(row + 8) * OUT_COLS + col + 1] = acc[mf][nf][3];
        }
    }

    // ---- rowsum column (0) ----
    if (do_extra && tid < MT) {
        out[(size_t)(m0 + tid) * OUT_COLS] = rowsum[tid];
    }
}

extern "C" void kernel_launch(void* const* d_in, const int* in_sizes, int n_in,
                              void* d_out, int out_size)
{
    const float* x = (const float*)d_in[0];   // (131072, 512)
    const float* w = (const float*)d_in[1];   // (512, 512)
    float* out = (float*)d_out;               // (131072, 1025)

    dim3 grid(NOUT / NT, M_TOTAL / MT);       // (4, 1024)
    lola_fused_kernel<<<grid, 256>>>(x, w, out);
}

// round 2
// speedup vs baseline: 1.2083x; 1.2083x over previous
#include <cuda_runtime.h>
#include <cstdint>

// LoLa: out[m,0]=rowsum(x); out[m,1:513]=x; out[m,513:1025]=x@w
// M=131072, K=512, NOUT=512, OUT_COLS=1025, fp32.

#define M_TOTAL   131072
#define KDIM      512
#define NOUT      512
#define OUT_COLS  1025

#define MT 128
#define NT 128
#define KT 32
#define NKTILES (KDIM / KT)   // 16

#define XS_STRIDE 36          // bank = (4r+c)%32 -> conflict-free
#define WS_STRIDE 136         // bank = (8k+n)%32 -> conflict-free

// w pre-converted to tf32 (RNA) once per launch.
__device__ uint32_t g_w_tf32[KDIM * NOUT];

__device__ __forceinline__ uint32_t f2tf32(float f) {
    uint32_t u;
    asm("cvt.rna.tf32.f32 %0, %1;" : "=r"(u) : "f"(f));
    return u;
}

__device__ __forceinline__ void cp_async16(uint32_t smem_addr, const void* gptr) {
    asm volatile("cp.async.cg.shared.global [%0], [%1], 16;\n"
                 :: "r"(smem_addr), "l"(gptr));
}
__device__ __forceinline__ void cp_commit() {
    asm volatile("cp.async.commit_group;\n" ::);
}
template <int N>
__device__ __forceinline__ void cp_wait() {
    asm volatile("cp.async.wait_group %0;\n" :: "n"(N));
}

__global__ void w_convert_kernel(const float* __restrict__ w) {
    int i = (blockIdx.x * 256 + threadIdx.x) * 4;   // 256 blocks x 256 thr x 4
    float4 v = *(const float4*)&w[i];
    uint4 t;
    t.x = f2tf32(v.x); t.y = f2tf32(v.y); t.z = f2tf32(v.z); t.w = f2tf32(v.w);
    *(uint4*)&g_w_tf32[i] = t;
}

__global__ __launch_bounds__(256, 2)
void lola_fused_kernel(const float* __restrict__ x,
                       float* __restrict__ out)
{
    __shared__ uint32_t xs[2][MT][XS_STRIDE];   // raw fp32 bits (tf32 by truncation)
    __shared__ uint32_t ws[2][KT][WS_STRIDE];   // tf32 bits

    const int nb   = blockIdx.x;                // 0..3
    const int mb   = blockIdx.y;                // 0..1023
    const int m0   = mb * MT;
    const int n0   = nb * NT;
    const int tid  = threadIdx.x;
    const int lane = tid & 31;
    const int warp = tid >> 5;
    const int warp_m = warp >> 2;               // 0..1
    const int warp_n = warp & 3;                // 0..3
    const bool do_extra = (nb == 0);

    float psum[4] = {0.f, 0.f, 0.f, 0.f};       // rowsum partials, rows (tid>>3)+32i

    float acc[4][4][4];
    #pragma unroll
    for (int i = 0; i < 4; i++)
        #pragma unroll
        for (int j = 0; j < 4; j++)
            #pragma unroll
            for (int k = 0; k < 4; k++)
                acc[i][j][k] = 0.0f;

    // ---- async stage of one k-tile ----
    auto stage = [&](int kt) {
        const int k0 = kt * KT;
        const int buf = kt & 1;
        #pragma unroll
        for (int i = 0; i < 4; i++) {
            int idx = tid + i * 256;
            int r   = idx >> 3;                 // 0..127
            int c   = (idx & 7) * 4;            // 0..28
            cp_async16(__cvta_generic_to_shared(&xs[buf][r][c]),
                       &x[(size_t)(m0 + r) * KDIM + k0 + c]);
        }
        #pragma unroll
        for (int i = 0; i < 4; i++) {
            int idx = tid + i * 256;
            int r   = idx >> 5;                 // 0..31
            int c   = (idx & 31) * 4;           // 0..124
            cp_async16(__cvta_generic_to_shared(&ws[buf][r][c]),
                       &g_w_tf32[(size_t)(k0 + r) * NOUT + n0 + c]);
        }
        cp_commit();
    };

    // ---- fused copy + rowsum (nb==0 only); LDG hits L2 behind cp.async ----
    auto copy_path = [&](int kt) {
        const int k0 = kt * KT;
        #pragma unroll
        for (int i = 0; i < 4; i++) {
            int idx = tid + i * 256;
            int r   = idx >> 3;
            int c   = (idx & 7) * 4;
            float4 v = *(const float4*)&x[(size_t)(m0 + r) * KDIM + k0 + c];
            float* o = &out[(size_t)(m0 + r) * OUT_COLS + 1 + k0 + c];
            o[0] = v.x; o[1] = v.y; o[2] = v.z; o[3] = v.w;
            psum[i] += (v.x + v.y) + (v.z + v.w);
        }
    };

    // ---- compute one staged k-tile ----
    auto compute = [&](int buf) {
        #pragma unroll
        for (int kk = 0; kk < KT; kk += 8) {
            uint32_t bfrag[4][2];
            #pragma unroll
            for (int nf = 0; nf < 4; nf++) {
                int col = warp_n * 32 + nf * 8 + (lane >> 2);
                bfrag[nf][0] = ws[buf][kk + (lane & 3)][col];
                bfrag[nf][1] = ws[buf][kk + (lane & 3) + 4][col];
            }
            uint32_t afrag[4][4];
            #pragma unroll
            for (int mf = 0; mf < 4; mf++) {
                int row = warp_m * 64 + mf * 16 + (lane >> 2);
                int c0  = kk + (lane & 3);
                afrag[mf][0] = xs[buf][row][c0];
                afrag[mf][1] = xs[buf][row + 8][c0];
                afrag[mf][2] = xs[buf][row][c0 + 4];
                afrag[mf][3] = xs[buf][row + 8][c0 + 4];
            }
            #pragma unroll
            for (int mf = 0; mf < 4; mf++) {
                #pragma unroll
                for (int nf = 0; nf < 4; nf++) {
                    asm volatile(
                        "mma.sync.aligned.m16n8k8.row.col.f32.tf32.tf32.f32 "
                        "{%0,%1,%2,%3}, {%4,%5,%6,%7}, {%8,%9}, {%0,%1,%2,%3};"
                        : "+f"(acc[mf][nf][0]), "+f"(acc[mf][nf][1]),
                          "+f"(acc[mf][nf][2]), "+f"(acc[mf][nf][3])
                        : "r"(afrag[mf][0]), "r"(afrag[mf][1]),
                          "r"(afrag[mf][2]), "r"(afrag[mf][3]),
                          "r"(bfrag[nf][0]), "r"(bfrag[nf][1]));
                }
            }
        }
    };

    // ---- pipelined mainloop ----
    stage(0);
    #pragma unroll 1
    for (int kt = 0; kt < NKTILES; kt++) {
        if (kt + 1 < NKTILES) {
            stage(kt + 1);
            cp_wait<1>();
        } else {
            cp_wait<0>();
        }
        __syncthreads();
        if (do_extra) copy_path(kt);
        compute(kt & 1);
        __syncthreads();   // protect buf (kt&1) from stage(kt+2)
    }

    // ---- epilogue: GEMM columns 513..1024 ----
    #pragma unroll
    for (int mf = 0; mf < 4; mf++) {
        int row = m0 + warp_m * 64 + mf * 16 + (lane >> 2);
        #pragma unroll
        for (int nf = 0; nf < 4; nf++) {
            int col = 513 + n0 + warp_n * 32 + nf * 8 + (lane & 3) * 2;
            out[(size_t)row * OUT_COLS + col]           = acc[mf][nf][0];
            out[(size_t)row * OUT_COLS + col + 1]       = acc[mf][nf][1];
            out[(size_t)(row + 8) * OUT_COLS + col]     = acc[mf][nf][2];
            out[(size_t)(row + 8) * OUT_COLS + col + 1] = acc[mf][nf][3];
        }
    }

    // ---- rowsum column 0 (reduce 8 threads per row via shfl) ----
    if (do_extra) {
        #pragma unroll
        for (int i = 0; i < 4; i++) {
            float s = psum[i];
            s += __shfl_xor_sync(0xffffffffu, s, 1);
            s += __shfl_xor_sync(0xffffffffu, s, 2);
            s += __shfl_xor_sync(0xffffffffu, s, 4);
            if ((lane & 7) == 0)
                out[(size_t)(m0 + (tid >> 3) + 32 * i) * OUT_COLS] = s;
        }
    }
}

extern "C" void kernel_launch(void* const* d_in, const int* in_sizes, int n_in,
                              void* d_out, int out_size)
{
    const float* x = (const float*)d_in[0];   // (131072, 512)
    const float* w = (const float*)d_in[1];   // (512, 512)
    float* out = (float*)d_out;               // (131072, 1025)

    w_convert_kernel<<<256, 256>>>(w);        // 512*512 = 256*256*4
    dim3 grid(NOUT / NT, M_TOTAL / MT);       // (4, 1024)
    lola_fused_kernel<<<grid, 256>>>(x, out);
}